// round 15
// baseline (speedup 1.0000x reference)
#include <cuda_runtime.h>
#include <cuda_bf16.h>
#include <cstdint>

#define D_MODEL 1024
#define STATE   128
#define BATCH   4
#define SEQ     4096
#define ROWS    (BATCH*SEQ)     /* 16384 */
#define NCHUNK  32
#define DC      32              /* D per scan chunk */
#define TS      16              /* scan steps per tile */
#define RMS_EPS 1.1920929e-07f

// k_scan dynamic smem layout (floats)
#define XS_OFF   0            /* 2 x 16 x 32   = 1024  */
#define BS_OFF   1024         /* 2 x 16 x 128  = 4096  */
#define OUT_OFF  5120         /* 8 x 16 x 128  = 16384 */
#define SCAN_SMEM_BYTES (21504 * 4)   /* 84 KB */

// ---------------- scratch (static device arrays; no runtime alloc) ----------------
__device__ float          g_x   [ROWS*D_MODEL];     // gathered embeddings, 67MB
__device__ float          g_bt  [ROWS*STATE];       // sigmoid(x @ W_B^T)/1024, 8MB
__device__ float          g_hm  [ROWS*STATE];       // reduced state means, 8MB
__device__ float          g_wbt [D_MODEL*STATE];    // W_B transposed: [k][n]
__device__ float          g_wct [STATE*D_MODEL];    // W_C transposed: [n][d]
__device__ __nv_bfloat16  g_part[NCHUNK*ROWS*STATE];// per-chunk partial sums, 134MB

// ---------------- helpers ----------------
__device__ __forceinline__ unsigned long long pk2(float lo, float hi) {
    unsigned long long r; asm("mov.b64 %0,{%1,%2};" : "=l"(r) : "f"(lo), "f"(hi)); return r;
}
__device__ __forceinline__ void upk2(unsigned long long v, float& lo, float& hi) {
    asm("mov.b64 {%0,%1},%2;" : "=f"(lo), "=f"(hi) : "l"(v));
}
__device__ __forceinline__ unsigned long long fma2(unsigned long long a, unsigned long long b, unsigned long long c) {
    unsigned long long r; asm("fma.rn.f32x2 %0,%1,%2,%3;" : "=l"(r) : "l"(a), "l"(b), "l"(c)); return r;
}
__device__ __forceinline__ unsigned long long mul2(unsigned long long a, unsigned long long b) {
    unsigned long long r; asm("mul.rn.f32x2 %0,%1,%2;" : "=l"(r) : "l"(a), "l"(b)); return r;
}
__device__ __forceinline__ unsigned long long add2(unsigned long long a, unsigned long long b) {
    unsigned long long r; asm("add.rn.f32x2 %0,%1,%2;" : "=l"(r) : "l"(a), "l"(b)); return r;
}
__device__ __forceinline__ float sigmoidf_(float x) { return 1.0f / (1.0f + __expf(-x)); }

__device__ __forceinline__ void cpasync16(void* smem, const void* gmem) {
    unsigned s = (unsigned)__cvta_generic_to_shared(smem);
    asm volatile("cp.async.cg.shared.global [%0],[%1],16;" :: "r"(s), "l"(gmem));
}
#define CP_COMMIT() asm volatile("cp.async.commit_group;")
#define CP_WAIT0()  asm volatile("cp.async.wait_group 0;")

// ---------------- K0: transpose weights ----------------
__global__ void k_prep(const float* __restrict__ WB, const float* __restrict__ WC) {
    int i = blockIdx.x * 256 + threadIdx.x;            // 131072 total
    if (i < D_MODEL * STATE) {
        int k = i >> 7, n = i & 127;                    // g_wbt[k][n] = W_B[n][k]
        g_wbt[i] = WB[n * D_MODEL + k];
        int nn = i >> 10, d = i & 1023;                 // g_wct[n][d] = W_C[d][n]
        g_wct[i] = WC[d * STATE + nn];
    }
}

// ---------------- K1: embedding gather ----------------
__global__ void k_gather(const int* __restrict__ tokens, const float* __restrict__ emb) {
    int row = blockIdx.x;
    int tok = tokens[row];
    const float4* src = (const float4*)(emb + (size_t)tok * D_MODEL);
    float4* dst = (float4*)(g_x + (size_t)row * D_MODEL);
    dst[threadIdx.x] = src[threadIdx.x];                // 256 thr x 16B = 4KB
}

// ---------------- K2: Bt = sigmoid(x @ W_B^T)/1024  [16384x1024]x[1024x128] ----------------
// 256 threads, 8x8 micro-tile (best measured).
__global__ void __launch_bounds__(256, 1) k_gemm_bt() {
    __shared__ float As[2][128 * 8];   // [row][kk]
    __shared__ float Bs[2][8 * 128];   // [kk][n]
    int t = threadIdx.x;
    int row0 = blockIdx.x * 128;
    int tr = t >> 4, tc = t & 15;

    unsigned long long acc[8][4];
    #pragma unroll
    for (int i = 0; i < 8; i++)
        #pragma unroll
        for (int j = 0; j < 4; j++) acc[i][j] = 0ull;

    {
        int r = t >> 1, q = t & 1;
        cpasync16(&As[0][r * 8 + q * 4], &g_x[(size_t)(row0 + r) * D_MODEL + q * 4]);
        int kk = t >> 5, q2 = t & 31;
        cpasync16(&Bs[0][kk * 128 + q2 * 4], &g_wbt[kk * STATE + q2 * 4]);
        CP_COMMIT();
    }

    const int NT = D_MODEL / 8;   // 128 k-tiles
    for (int kt = 0; kt < NT; kt++) {
        CP_WAIT0();
        __syncthreads();
        if (kt + 1 < NT) {
            int k0 = (kt + 1) * 8, buf = (kt + 1) & 1;
            int r = t >> 1, q = t & 1;
            cpasync16(&As[buf][r * 8 + q * 4], &g_x[(size_t)(row0 + r) * D_MODEL + k0 + q * 4]);
            int kk = t >> 5, q2 = t & 31;
            cpasync16(&Bs[buf][kk * 128 + q2 * 4], &g_wbt[(k0 + kk) * STATE + q2 * 4]);
            CP_COMMIT();
        }
        const float* Ab = &As[kt & 1][0];
        const float* Bb = &Bs[kt & 1][0];
        #pragma unroll
        for (int kk = 0; kk < 8; kk++) {
            float4 b0 = *(const float4*)&Bb[kk * 128 + tc * 8];
            float4 b1 = *(const float4*)&Bb[kk * 128 + tc * 8 + 4];
            unsigned long long bp[4] = { pk2(b0.x, b0.y), pk2(b0.z, b0.w),
                                         pk2(b1.x, b1.y), pk2(b1.z, b1.w) };
            #pragma unroll
            for (int i = 0; i < 8; i++) {
                float a = Ab[(tr * 8 + i) * 8 + kk];
                unsigned long long ad = pk2(a, a);
                #pragma unroll
                for (int j = 0; j < 4; j++) acc[i][j] = fma2(ad, bp[j], acc[i][j]);
            }
        }
        __syncthreads();
    }

    // epilogue: sigmoid * (1/1024) + store  (1/1024 folded: linear recurrence scales h,
    // so the scan's emitted partial sums come out already in mean units)
    #pragma unroll
    for (int i = 0; i < 8; i++) {
        int row = row0 + tr * 8 + i;
        float o[8];
        #pragma unroll
        for (int j = 0; j < 4; j++) upk2(acc[i][j], o[2 * j], o[2 * j + 1]);
        #pragma unroll
        for (int j = 0; j < 8; j++) o[j] = sigmoidf_(o[j]) * 0.0009765625f;
        float* dst = &g_bt[(size_t)row * STATE + tc * 8];
        *(float4*)(dst)     = make_float4(o[0], o[1], o[2], o[3]);
        *(float4*)(dst + 4) = make_float4(o[4], o[5], o[6], o[7]);
    }
}

// ---------------- K3: the scan ----------------
// grid = 128 CTAs: (b, chunk). 1024 threads: (eighth, n). Eighth owns 4 d's
// (2 f32x2 pairs) -> 8 warps/SMSP, short per-step body (~11 inst) to hide LDS.
// Dynamic smem 84KB (fp32 out slabs, TS=16 tiles).
__global__ void __launch_bounds__(1024, 1) k_scan(const float* __restrict__ A_log) {
    extern __shared__ float sm[];

    int tid = threadIdx.x;
    int et  = tid >> 7;                    // 0..7: which 4-d sub-chunk
    int nid = tid & 127;                   // state index n
    int c = blockIdx.x & 31;               // chunk
    int b = blockIdx.x >> 5;               // batch
    int d0 = c * DC;
    int dbase = d0 + et * 4;
    int rbase = b * SEQ;

    // decay factors (2 pairs over d)
    unsigned long long a2[2], h2[2];
    #pragma unroll
    for (int j = 0; j < 2; j++) {
        float alo = sigmoidf_(A_log[(dbase + 2 * j)     * STATE + nid]);
        float ahi = sigmoidf_(A_log[(dbase + 2 * j + 1) * STATE + nid]);
        a2[j] = pk2(alo, ahi);
        h2[j] = 0ull;
    }

    // prologue: tile 0  (xs = 16x32 f32 = 2KB -> 128 loads; bs = 16x128 f32 = 8KB -> 512 loads)
    {
        if (tid < 128) {
            int ss = tid >> 3, q = tid & 7;
            cpasync16(&sm[XS_OFF + ss * 32 + q * 4],
                      &g_x[(size_t)(rbase + ss) * D_MODEL + d0 + q * 4]);
        } else if (tid >= 512) {
            int idx = tid - 512, s2 = idx >> 5, q2 = idx & 31;
            cpasync16(&sm[BS_OFF + s2 * 128 + q2 * 4],
                      &g_bt[(size_t)(rbase + s2) * STATE + q2 * 4]);
        }
        CP_COMMIT();
    }

    const int NT = SEQ / TS;   // 256 tiles
    for (int tt = 0; tt < NT; tt++) {
        CP_WAIT0();
        __syncthreads();   // tile data ready; also: prev flush done -> outs reusable
        if (tt + 1 < NT) {
            int s0n = (tt + 1) * TS, buf = (tt + 1) & 1;
            if (tid < 128) {
                int ss = tid >> 3, q = tid & 7;
                cpasync16(&sm[XS_OFF + buf * 512 + ss * 32 + q * 4],
                          &g_x[(size_t)(rbase + s0n + ss) * D_MODEL + d0 + q * 4]);
            } else if (tid >= 512) {
                int idx = tid - 512, s2 = idx >> 5, q2 = idx & 31;
                cpasync16(&sm[BS_OFF + buf * 2048 + s2 * 128 + q2 * 4],
                          &g_bt[(size_t)(rbase + s0n + s2) * STATE + q2 * 4]);
            }
            CP_COMMIT();
        }
        int cur = tt & 1;
        const float* xb = &sm[XS_OFF + cur * 512];
        const float* bb = &sm[BS_OFF + cur * 2048];
        float* ob = &sm[OUT_OFF + et * 2048];
        #pragma unroll
        for (int ss = 0; ss < TS; ss++) {
            float btv = bb[ss * 128 + nid];
            unsigned long long bt2 = pk2(btv, btv);
            const unsigned long long* xp =
                (const unsigned long long*)&xb[ss * 32 + et * 4];
            unsigned long long t0 = mul2(bt2, xp[0]);
            unsigned long long t1 = mul2(bt2, xp[1]);
            h2[0] = fma2(a2[0], h2[0], t0);
            h2[1] = fma2(a2[1], h2[1], t1);
            unsigned long long st = add2(h2[0], h2[1]);
            float lo, hi; upk2(st, lo, hi);
            ob[ss * 128 + nid] = lo + hi;     // already in mean units (bt folded)
        }
        __syncthreads();
        // flush: combine 8 eighths in fp32, cvt bf16, 4B/thread to g_part
        {
            int s = tid >> 6, g = tid & 63;   // 16 rows x 64 thr, 2 n each
            float w0 = 0.0f, w1 = 0.0f;
            #pragma unroll
            for (int q = 0; q < 8; q++) {
                float2 v = *(const float2*)&sm[OUT_OFF + q * 2048 + s * 128 + g * 2];
                w0 += v.x; w1 += v.y;
            }
            __nv_bfloat162 p0 = __floats2bfloat162_rn(w0, w1);
            size_t row = (size_t)c * ROWS + rbase + tt * TS + s;
            ((unsigned*)g_part)[row * 64 + g] = *(unsigned*)&p0;
        }
    }
}

// ---------------- K4: reduce partials -> hm ----------------
__global__ void k_reduce() {
    int g = blockIdx.x * 256 + threadIdx.x;   // 8192 blocks => 2.1M threads
    int row = g >> 7, n = g & 127;
    float s = 0.0f;
    #pragma unroll
    for (int c = 0; c < NCHUNK; c++)
        s += __bfloat162float(g_part[((size_t)c * ROWS + row) * STATE + n]);
    g_hm[(size_t)row * STATE + n] = s;
}

// ---------------- K5: y = hm @ W_C^T + D*x  (pre-norm), [16384x128]x[128x1024] ----------------
__global__ void __launch_bounds__(256, 1) k_gemm_y(float* __restrict__ out,
                                                   const float* __restrict__ Dp) {
    __shared__ float As[2][128 * 8];   // hm rows [row][kk]
    __shared__ float Bs[2][8 * 128];   // wct [kk][d]
    int t = threadIdx.x;
    int mt = blockIdx.x >> 3;
    int nt = blockIdx.x & 7;
    int row0 = mt * 128;
    int d0 = nt * 128;
    int tr = t >> 4, tc = t & 15;

    unsigned long long acc[8][4];
    #pragma unroll
    for (int i = 0; i < 8; i++)
        #pragma unroll
        for (int j = 0; j < 4; j++) acc[i][j] = 0ull;

    {
        int r = t >> 1, q = t & 1;
        cpasync16(&As[0][r * 8 + q * 4], &g_hm[(size_t)(row0 + r) * STATE + q * 4]);
        int kk = t >> 5, q2 = t & 31;
        cpasync16(&Bs[0][kk * 128 + q2 * 4], &g_wct[(size_t)kk * D_MODEL + d0 + q2 * 4]);
        CP_COMMIT();
    }

    const int NT = STATE / 8;  // 16 k-tiles
    for (int kt = 0; kt < NT; kt++) {
        CP_WAIT0();
        __syncthreads();
        if (kt + 1 < NT) {
            int k0 = (kt + 1) * 8, buf = (kt + 1) & 1;
            int r = t >> 1, q = t & 1;
            cpasync16(&As[buf][r * 8 + q * 4], &g_hm[(size_t)(row0 + r) * STATE + k0 + q * 4]);
            int kk = t >> 5, q2 = t & 31;
            cpasync16(&Bs[buf][kk * 128 + q2 * 4], &g_wct[(size_t)(k0 + kk) * D_MODEL + d0 + q2 * 4]);
            CP_COMMIT();
        }
        const float* Ab = &As[kt & 1][0];
        const float* Bb = &Bs[kt & 1][0];
        #pragma unroll
        for (int kk = 0; kk < 8; kk++) {
            float4 b0 = *(const float4*)&Bb[kk * 128 + tc * 8];
            float4 b1 = *(const float4*)&Bb[kk * 128 + tc * 8 + 4];
            unsigned long long bp[4] = { pk2(b0.x, b0.y), pk2(b0.z, b0.w),
                                         pk2(b1.x, b1.y), pk2(b1.z, b1.w) };
            #pragma unroll
            for (int i = 0; i < 8; i++) {
                float a = Ab[(tr * 8 + i) * 8 + kk];
                unsigned long long ad = pk2(a, a);
                #pragma unroll
                for (int j = 0; j < 4; j++) acc[i][j] = fma2(ad, bp[j], acc[i][j]);
            }
        }
        __syncthreads();
    }

    // epilogue: + D_param*x, store pre-norm y
    float4 dpa = *(const float4*)&Dp[d0 + tc * 8];
    float4 dpb = *(const float4*)&Dp[d0 + tc * 8 + 4];
    #pragma unroll
    for (int i = 0; i < 8; i++) {
        int row = row0 + tr * 8 + i;
        const float* xr = &g_x[(size_t)row * D_MODEL + d0 + tc * 8];
        float4 xa = *(const float4*)xr;
        float4 xb = *(const float4*)(xr + 4);
        float o[8];
        #pragma unroll
        for (int j = 0; j < 4; j++) upk2(acc[i][j], o[2 * j], o[2 * j + 1]);
        o[0] += dpa.x * xa.x; o[1] += dpa.y * xa.y; o[2] += dpa.z * xa.z; o[3] += dpa.w * xa.w;
        o[4] += dpb.x * xb.x; o[5] += dpb.y * xb.y; o[6] += dpb.z * xb.z; o[7] += dpb.w * xb.w;
        float* dst = out + (size_t)row * D_MODEL + d0 + tc * 8;
        *(float4*)(dst)     = make_float4(o[0], o[1], o[2], o[3]);
        *(float4*)(dst + 4) = make_float4(o[4], o[5], o[6], o[7]);
    }
}

// ---------------- K6: RMSNorm in place ----------------
__global__ void k_rms(float* __restrict__ out, const float* __restrict__ w) {
    int row = blockIdx.x;
    int t = threadIdx.x;
    float4* p = (float4*)(out + (size_t)row * D_MODEL);
    float4 v = p[t];
    float ss = v.x * v.x + v.y * v.y + v.z * v.z + v.w * v.w;
    #pragma unroll
    for (int off = 16; off > 0; off >>= 1) ss += __shfl_xor_sync(0xffffffffu, ss, off);
    __shared__ float red[8];
    if ((t & 31) == 0) red[t >> 5] = ss;
    __syncthreads();
    if (t < 32) {
        float v2 = (t < 8) ? red[t] : 0.0f;
        #pragma unroll
        for (int off = 4; off > 0; off >>= 1) v2 += __shfl_xor_sync(0xffffffffu, v2, off);
        if (t == 0) red[0] = v2;
    }
    __syncthreads();
    float sc = rsqrtf(red[0] * (1.0f / 1024.0f) + RMS_EPS);
    const float4* w4 = (const float4*)w;
    float4 wv = w4[t];
    v.x *= sc * wv.x; v.y *= sc * wv.y; v.z *= sc * wv.z; v.w *= sc * wv.w;
    p[t] = v;
}

// ---------------- launch ----------------
extern "C" void kernel_launch(void* const* d_in, const int* in_sizes, int n_in,
                              void* d_out, int out_size) {
    (void)in_sizes; (void)n_in; (void)out_size;
    const int*   tokens = (const int*)  d_in[0];
    const float* emb    = (const float*)d_in[1];
    const float* A_log  = (const float*)d_in[2];
    const float* W_B    = (const float*)d_in[3];
    const float* W_C    = (const float*)d_in[4];
    const float* Dp     = (const float*)d_in[5];
    const float* nw     = (const float*)d_in[6];
    float* out = (float*)d_out;

    // opt-in to >48KB dynamic smem for k_scan (idempotent; no stream op, capture-safe)
    cudaFuncSetAttribute(k_scan, cudaFuncAttributeMaxDynamicSharedMemorySize,
                         SCAN_SMEM_BYTES);

    k_prep<<<512, 256>>>(W_B, W_C);
    k_gather<<<ROWS, 256>>>(tokens, emb);
    k_gemm_bt<<<ROWS / 128, 256>>>();
    k_scan<<<BATCH * NCHUNK, 1024, SCAN_SMEM_BYTES>>>(A_log);
    k_reduce<<<ROWS * STATE / 256, 256>>>();
    k_gemm_y<<<(ROWS / 128) * (D_MODEL / 128), 256>>>(out, Dp);
    k_rms<<<ROWS, 256>>>(out, nw);
}

// round 16
// speedup vs baseline: 1.1359x; 1.1359x over previous
#include <cuda_runtime.h>
#include <cuda_bf16.h>
#include <cstdint>

#define D_MODEL 1024
#define STATE   128
#define BATCH   4
#define SEQ     4096
#define ROWS    (BATCH*SEQ)     /* 16384 */
#define NCHUNK  32
#define DC      32              /* D per scan chunk */
#define TS      32              /* scan steps per tile */
#define RMS_EPS 1.1920929e-07f

// k_scan dynamic smem layout (floats) — R11-proven 104KB footprint
#define XS_OFF   0            /* 2 x 32 x 32   = 2048  */
#define BS_OFF   2048         /* 2 x 32 x 128  = 8192  */
#define OUT_OFF  10240        /* 4 x 32 x 128  = 16384 */
#define SCAN_SMEM_BYTES (26624 * 4)   /* 104 KB */

// ---------------- scratch (static device arrays; no runtime alloc) ----------------
__device__ float          g_x   [ROWS*D_MODEL];     // gathered embeddings, 67MB
__device__ float          g_bt  [ROWS*STATE];       // sigmoid(x @ W_B^T)/1024, 8MB
__device__ float          g_hm  [ROWS*STATE];       // reduced state means, 8MB
__device__ float          g_wbt [D_MODEL*STATE];    // W_B transposed: [k][n]
__device__ float          g_wct [STATE*D_MODEL];    // W_C transposed: [n][d]
__device__ __nv_bfloat16  g_part[NCHUNK*ROWS*STATE];// per-chunk partial sums, 134MB

// ---------------- helpers ----------------
__device__ __forceinline__ unsigned long long pk2(float lo, float hi) {
    unsigned long long r; asm("mov.b64 %0,{%1,%2};" : "=l"(r) : "f"(lo), "f"(hi)); return r;
}
__device__ __forceinline__ void upk2(unsigned long long v, float& lo, float& hi) {
    asm("mov.b64 {%0,%1},%2;" : "=f"(lo), "=f"(hi) : "l"(v));
}
__device__ __forceinline__ unsigned long long fma2(unsigned long long a, unsigned long long b, unsigned long long c) {
    unsigned long long r; asm("fma.rn.f32x2 %0,%1,%2,%3;" : "=l"(r) : "l"(a), "l"(b), "l"(c)); return r;
}
__device__ __forceinline__ unsigned long long mul2(unsigned long long a, unsigned long long b) {
    unsigned long long r; asm("mul.rn.f32x2 %0,%1,%2;" : "=l"(r) : "l"(a), "l"(b)); return r;
}
__device__ __forceinline__ unsigned long long add2(unsigned long long a, unsigned long long b) {
    unsigned long long r; asm("add.rn.f32x2 %0,%1,%2;" : "=l"(r) : "l"(a), "l"(b)); return r;
}
__device__ __forceinline__ float sigmoidf_(float x) { return 1.0f / (1.0f + __expf(-x)); }

__device__ __forceinline__ void cpasync16(void* smem, const void* gmem) {
    unsigned s = (unsigned)__cvta_generic_to_shared(smem);
    asm volatile("cp.async.cg.shared.global [%0],[%1],16;" :: "r"(s), "l"(gmem));
}
#define CP_COMMIT() asm volatile("cp.async.commit_group;")
#define CP_WAIT0()  asm volatile("cp.async.wait_group 0;")

// ---------------- K0: transpose weights ----------------
__global__ void k_prep(const float* __restrict__ WB, const float* __restrict__ WC) {
    int i = blockIdx.x * 256 + threadIdx.x;            // 131072 total
    if (i < D_MODEL * STATE) {
        int k = i >> 7, n = i & 127;                    // g_wbt[k][n] = W_B[n][k]
        g_wbt[i] = WB[n * D_MODEL + k];
        int nn = i >> 10, d = i & 1023;                 // g_wct[n][d] = W_C[d][n]
        g_wct[i] = WC[d * STATE + nn];
    }
}

// ---------------- K1: embedding gather ----------------
__global__ void k_gather(const int* __restrict__ tokens, const float* __restrict__ emb) {
    int row = blockIdx.x;
    int tok = tokens[row];
    const float4* src = (const float4*)(emb + (size_t)tok * D_MODEL);
    float4* dst = (float4*)(g_x + (size_t)row * D_MODEL);
    dst[threadIdx.x] = src[threadIdx.x];                // 256 thr x 16B = 4KB
}

// ---------------- K2: Bt = sigmoid(x @ W_B^T)/1024  [16384x1024]x[1024x128] ----------------
// 256 threads, 8x8 micro-tile (best measured).
__global__ void __launch_bounds__(256, 1) k_gemm_bt() {
    __shared__ float As[2][128 * 8];   // [row][kk]
    __shared__ float Bs[2][8 * 128];   // [kk][n]
    int t = threadIdx.x;
    int row0 = blockIdx.x * 128;
    int tr = t >> 4, tc = t & 15;

    unsigned long long acc[8][4];
    #pragma unroll
    for (int i = 0; i < 8; i++)
        #pragma unroll
        for (int j = 0; j < 4; j++) acc[i][j] = 0ull;

    {
        int r = t >> 1, q = t & 1;
        cpasync16(&As[0][r * 8 + q * 4], &g_x[(size_t)(row0 + r) * D_MODEL + q * 4]);
        int kk = t >> 5, q2 = t & 31;
        cpasync16(&Bs[0][kk * 128 + q2 * 4], &g_wbt[kk * STATE + q2 * 4]);
        CP_COMMIT();
    }

    const int NT = D_MODEL / 8;   // 128 k-tiles
    for (int kt = 0; kt < NT; kt++) {
        CP_WAIT0();
        __syncthreads();
        if (kt + 1 < NT) {
            int k0 = (kt + 1) * 8, buf = (kt + 1) & 1;
            int r = t >> 1, q = t & 1;
            cpasync16(&As[buf][r * 8 + q * 4], &g_x[(size_t)(row0 + r) * D_MODEL + k0 + q * 4]);
            int kk = t >> 5, q2 = t & 31;
            cpasync16(&Bs[buf][kk * 128 + q2 * 4], &g_wbt[(k0 + kk) * STATE + q2 * 4]);
            CP_COMMIT();
        }
        const float* Ab = &As[kt & 1][0];
        const float* Bb = &Bs[kt & 1][0];
        #pragma unroll
        for (int kk = 0; kk < 8; kk++) {
            float4 b0 = *(const float4*)&Bb[kk * 128 + tc * 8];
            float4 b1 = *(const float4*)&Bb[kk * 128 + tc * 8 + 4];
            unsigned long long bp[4] = { pk2(b0.x, b0.y), pk2(b0.z, b0.w),
                                         pk2(b1.x, b1.y), pk2(b1.z, b1.w) };
            #pragma unroll
            for (int i = 0; i < 8; i++) {
                float a = Ab[(tr * 8 + i) * 8 + kk];
                unsigned long long ad = pk2(a, a);
                #pragma unroll
                for (int j = 0; j < 4; j++) acc[i][j] = fma2(ad, bp[j], acc[i][j]);
            }
        }
        __syncthreads();
    }

    // epilogue: sigmoid * (1/1024) + store  (1/1024 folded: linear recurrence scales h,
    // so the scan's emitted partial sums come out already in mean units)
    #pragma unroll
    for (int i = 0; i < 8; i++) {
        int row = row0 + tr * 8 + i;
        float o[8];
        #pragma unroll
        for (int j = 0; j < 4; j++) upk2(acc[i][j], o[2 * j], o[2 * j + 1]);
        #pragma unroll
        for (int j = 0; j < 8; j++) o[j] = sigmoidf_(o[j]) * 0.0009765625f;
        float* dst = &g_bt[(size_t)row * STATE + tc * 8];
        *(float4*)(dst)     = make_float4(o[0], o[1], o[2], o[3]);
        *(float4*)(dst + 4) = make_float4(o[4], o[5], o[6], o[7]);
    }
}

// ---------------- K3: the scan ----------------
// grid = 128 CTAs: (b, chunk). 512 threads: (quarter, n). Quarter owns 8 d's (4 f32x2).
// Software-pipelined inner loop: step ss+1's bt/x prefetched into registers while
// step ss computes -> LDS latency hidden inside each warp. x loads are LDS.128
// broadcasts (halved crossbar phases vs LDS.64).
__global__ void __launch_bounds__(512, 1) k_scan(const float* __restrict__ A_log) {
    extern __shared__ float sm[];

    int tid = threadIdx.x;
    int qt  = tid >> 7;                    // 0..3: which 8-d sub-chunk
    int nid = tid & 127;                   // state index n
    int c = blockIdx.x & 31;               // chunk
    int b = blockIdx.x >> 5;               // batch
    int d0 = c * DC;
    int dbase = d0 + qt * 8;
    int rbase = b * SEQ;

    // decay factors (4 pairs over d)
    unsigned long long a2[4], h2[4];
    #pragma unroll
    for (int j = 0; j < 4; j++) {
        float alo = sigmoidf_(A_log[(dbase + 2 * j)     * STATE + nid]);
        float ahi = sigmoidf_(A_log[(dbase + 2 * j + 1) * STATE + nid]);
        a2[j] = pk2(alo, ahi);
        h2[j] = 0ull;
    }

    // prologue: tile 0  (xs tile = 32x32 f32 = 4KB; bs tile = 32x128 f32 = 16KB)
    {
        if (tid < 256) {
            int ss = tid >> 3, q = tid & 7;
            cpasync16(&sm[XS_OFF + ss * 32 + q * 4],
                      &g_x[(size_t)(rbase + ss) * D_MODEL + d0 + q * 4]);
        }
        #pragma unroll
        for (int jj = 0; jj < 2; jj++) {
            int idx = tid + 512 * jj, s2 = idx >> 5, q2 = idx & 31;
            cpasync16(&sm[BS_OFF + s2 * 128 + q2 * 4],
                      &g_bt[(size_t)(rbase + s2) * STATE + q2 * 4]);
        }
        CP_COMMIT();
    }

    const int NT = SEQ / TS;   // 128 tiles
    for (int tt = 0; tt < NT; tt++) {
        CP_WAIT0();
        __syncthreads();   // tile data ready; also: prev flush done -> outs reusable
        if (tt + 1 < NT) {
            int s0n = (tt + 1) * TS, buf = (tt + 1) & 1;
            if (tid < 256) {
                int ss = tid >> 3, q = tid & 7;
                cpasync16(&sm[XS_OFF + buf * 1024 + ss * 32 + q * 4],
                          &g_x[(size_t)(rbase + s0n + ss) * D_MODEL + d0 + q * 4]);
            }
            #pragma unroll
            for (int jj = 0; jj < 2; jj++) {
                int idx = tid + 512 * jj, s2 = idx >> 5, q2 = idx & 31;
                cpasync16(&sm[BS_OFF + buf * 4096 + s2 * 128 + q2 * 4],
                          &g_bt[(size_t)(rbase + s0n + s2) * STATE + q2 * 4]);
            }
            CP_COMMIT();
        }
        int cur = tt & 1;
        const float* xb = &sm[XS_OFF + cur * 1024];
        const float* bb = &sm[BS_OFF + cur * 4096];
        float* ob = &sm[OUT_OFF + qt * 4096];

        // peel: load step 0 operands into registers
        float btc = bb[nid];
        ulonglong2 xva = *(const ulonglong2*)&xb[qt * 8];       // d pairs 0,1 (16B bcast)
        ulonglong2 xvb = *(const ulonglong2*)&xb[qt * 8 + 4];   // d pairs 2,3

        #pragma unroll
        for (int ss = 0; ss < TS; ss++) {
            // prefetch step ss+1 while computing step ss
            float btn = 0.0f; ulonglong2 xna, xnb;
            if (ss + 1 < TS) {
                btn = bb[(ss + 1) * 128 + nid];
                xna = *(const ulonglong2*)&xb[(ss + 1) * 32 + qt * 8];
                xnb = *(const ulonglong2*)&xb[(ss + 1) * 32 + qt * 8 + 4];
            }
            unsigned long long bt2 = pk2(btc, btc);
            h2[0] = fma2(a2[0], h2[0], mul2(bt2, xva.x));
            h2[1] = fma2(a2[1], h2[1], mul2(bt2, xva.y));
            h2[2] = fma2(a2[2], h2[2], mul2(bt2, xvb.x));
            h2[3] = fma2(a2[3], h2[3], mul2(bt2, xvb.y));
            unsigned long long st = add2(add2(h2[0], h2[1]), add2(h2[2], h2[3]));
            float lo, hi; upk2(st, lo, hi);
            ob[ss * 128 + nid] = lo + hi;     // already in mean units (bt folded)
            btc = btn; xva = xna; xvb = xnb;  // rotate (register renaming under unroll)
        }
        __syncthreads();
        // flush: combine 4 quarters in fp32, cvt bf16, 16B/thread to g_part
        {
            int s = tid >> 4, g = tid & 15;   // 32 rows x 16 thr, 8 n each
            float w[8];
            #pragma unroll
            for (int k = 0; k < 8; k++) w[k] = 0.0f;
            #pragma unroll
            for (int q = 0; q < 4; q++) {
                const float4* p = (const float4*)&sm[OUT_OFF + q * 4096 + s * 128 + g * 8];
                float4 v0 = p[0], v1 = p[1];
                w[0] += v0.x; w[1] += v0.y; w[2] += v0.z; w[3] += v0.w;
                w[4] += v1.x; w[5] += v1.y; w[6] += v1.z; w[7] += v1.w;
            }
            __nv_bfloat162 p0 = __floats2bfloat162_rn(w[0], w[1]);
            __nv_bfloat162 p1 = __floats2bfloat162_rn(w[2], w[3]);
            __nv_bfloat162 p2 = __floats2bfloat162_rn(w[4], w[5]);
            __nv_bfloat162 p3 = __floats2bfloat162_rn(w[6], w[7]);
            uint4 pk;
            pk.x = *(unsigned*)&p0; pk.y = *(unsigned*)&p1;
            pk.z = *(unsigned*)&p2; pk.w = *(unsigned*)&p3;
            size_t row = (size_t)c * ROWS + rbase + tt * TS + s;
            ((uint4*)g_part)[row * 16 + g] = pk;
        }
    }
}

// ---------------- K4: reduce partials -> hm ----------------
__global__ void k_reduce() {
    int g = blockIdx.x * 256 + threadIdx.x;   // 8192 blocks => 2.1M threads
    int row = g >> 7, n = g & 127;
    float s = 0.0f;
    #pragma unroll
    for (int c = 0; c < NCHUNK; c++)
        s += __bfloat162float(g_part[((size_t)c * ROWS + row) * STATE + n]);
    g_hm[(size_t)row * STATE + n] = s;
}

// ---------------- K5: y = hm @ W_C^T + D*x  (pre-norm), [16384x128]x[128x1024] ----------------
__global__ void __launch_bounds__(256, 1) k_gemm_y(float* __restrict__ out,
                                                   const float* __restrict__ Dp) {
    __shared__ float As[2][128 * 8];   // hm rows [row][kk]
    __shared__ float Bs[2][8 * 128];   // wct [kk][d]
    int t = threadIdx.x;
    int mt = blockIdx.x >> 3;
    int nt = blockIdx.x & 7;
    int row0 = mt * 128;
    int d0 = nt * 128;
    int tr = t >> 4, tc = t & 15;

    unsigned long long acc[8][4];
    #pragma unroll
    for (int i = 0; i < 8; i++)
        #pragma unroll
        for (int j = 0; j < 4; j++) acc[i][j] = 0ull;

    {
        int r = t >> 1, q = t & 1;
        cpasync16(&As[0][r * 8 + q * 4], &g_hm[(size_t)(row0 + r) * STATE + q * 4]);
        int kk = t >> 5, q2 = t & 31;
        cpasync16(&Bs[0][kk * 128 + q2 * 4], &g_wct[(size_t)kk * D_MODEL + d0 + q2 * 4]);
        CP_COMMIT();
    }

    const int NT = STATE / 8;  // 16 k-tiles
    for (int kt = 0; kt < NT; kt++) {
        CP_WAIT0();
        __syncthreads();
        if (kt + 1 < NT) {
            int k0 = (kt + 1) * 8, buf = (kt + 1) & 1;
            int r = t >> 1, q = t & 1;
            cpasync16(&As[buf][r * 8 + q * 4], &g_hm[(size_t)(row0 + r) * STATE + k0 + q * 4]);
            int kk = t >> 5, q2 = t & 31;
            cpasync16(&Bs[buf][kk * 128 + q2 * 4], &g_wct[(size_t)(k0 + kk) * D_MODEL + d0 + q2 * 4]);
            CP_COMMIT();
        }
        const float* Ab = &As[kt & 1][0];
        const float* Bb = &Bs[kt & 1][0];
        #pragma unroll
        for (int kk = 0; kk < 8; kk++) {
            float4 b0 = *(const float4*)&Bb[kk * 128 + tc * 8];
            float4 b1 = *(const float4*)&Bb[kk * 128 + tc * 8 + 4];
            unsigned long long bp[4] = { pk2(b0.x, b0.y), pk2(b0.z, b0.w),
                                         pk2(b1.x, b1.y), pk2(b1.z, b1.w) };
            #pragma unroll
            for (int i = 0; i < 8; i++) {
                float a = Ab[(tr * 8 + i) * 8 + kk];
                unsigned long long ad = pk2(a, a);
                #pragma unroll
                for (int j = 0; j < 4; j++) acc[i][j] = fma2(ad, bp[j], acc[i][j]);
            }
        }
        __syncthreads();
    }

    // epilogue: + D_param*x, store pre-norm y
    float4 dpa = *(const float4*)&Dp[d0 + tc * 8];
    float4 dpb = *(const float4*)&Dp[d0 + tc * 8 + 4];
    #pragma unroll
    for (int i = 0; i < 8; i++) {
        int row = row0 + tr * 8 + i;
        const float* xr = &g_x[(size_t)row * D_MODEL + d0 + tc * 8];
        float4 xa = *(const float4*)xr;
        float4 xb = *(const float4*)(xr + 4);
        float o[8];
        #pragma unroll
        for (int j = 0; j < 4; j++) upk2(acc[i][j], o[2 * j], o[2 * j + 1]);
        o[0] += dpa.x * xa.x; o[1] += dpa.y * xa.y; o[2] += dpa.z * xa.z; o[3] += dpa.w * xa.w;
        o[4] += dpb.x * xb.x; o[5] += dpb.y * xb.y; o[6] += dpb.z * xb.z; o[7] += dpb.w * xb.w;
        float* dst = out + (size_t)row * D_MODEL + d0 + tc * 8;
        *(float4*)(dst)     = make_float4(o[0], o[1], o[2], o[3]);
        *(float4*)(dst + 4) = make_float4(o[4], o[5], o[6], o[7]);
    }
}

// ---------------- K6: RMSNorm in place ----------------
__global__ void k_rms(float* __restrict__ out, const float* __restrict__ w) {
    int row = blockIdx.x;
    int t = threadIdx.x;
    float4* p = (float4*)(out + (size_t)row * D_MODEL);
    float4 v = p[t];
    float ss = v.x * v.x + v.y * v.y + v.z * v.z + v.w * v.w;
    #pragma unroll
    for (int off = 16; off > 0; off >>= 1) ss += __shfl_xor_sync(0xffffffffu, ss, off);
    __shared__ float red[8];
    if ((t & 31) == 0) red[t >> 5] = ss;
    __syncthreads();
    if (t < 32) {
        float v2 = (t < 8) ? red[t] : 0.0f;
        #pragma unroll
        for (int off = 4; off > 0; off >>= 1) v2 += __shfl_xor_sync(0xffffffffu, v2, off);
        if (t == 0) red[0] = v2;
    }
    __syncthreads();
    float sc = rsqrtf(red[0] * (1.0f / 1024.0f) + RMS_EPS);
    const float4* w4 = (const float4*)w;
    float4 wv = w4[t];
    v.x *= sc * wv.x; v.y *= sc * wv.y; v.z *= sc * wv.z; v.w *= sc * wv.w;
    p[t] = v;
}

// ---------------- launch ----------------
extern "C" void kernel_launch(void* const* d_in, const int* in_sizes, int n_in,
                              void* d_out, int out_size) {
    (void)in_sizes; (void)n_in; (void)out_size;
    const int*   tokens = (const int*)  d_in[0];
    const float* emb    = (const float*)d_in[1];
    const float* A_log  = (const float*)d_in[2];
    const float* W_B    = (const float*)d_in[3];
    const float* W_C    = (const float*)d_in[4];
    const float* Dp     = (const float*)d_in[5];
    const float* nw     = (const float*)d_in[6];
    float* out = (float*)d_out;

    // opt-in to >48KB dynamic smem for k_scan (idempotent; no stream op, capture-safe)
    cudaFuncSetAttribute(k_scan, cudaFuncAttributeMaxDynamicSharedMemorySize,
                         SCAN_SMEM_BYTES);

    k_prep<<<512, 256>>>(W_B, W_C);
    k_gather<<<ROWS, 256>>>(tokens, emb);
    k_gemm_bt<<<ROWS / 128, 256>>>();
    k_scan<<<BATCH * NCHUNK, 512, SCAN_SMEM_BYTES>>>(A_log);
    k_reduce<<<ROWS * STATE / 256, 256>>>();
    k_gemm_y<<<(ROWS / 128) * (D_MODEL / 128), 256>>>(out, Dp);
    k_rms<<<ROWS, 256>>>(out, nw);
}

// round 17
// speedup vs baseline: 1.1425x; 1.0058x over previous
#include <cuda_runtime.h>
#include <cuda_bf16.h>
#include <cstdint>

#define D_MODEL 1024
#define STATE   128
#define BATCH   4
#define SEQ     4096
#define ROWS    (BATCH*SEQ)     /* 16384 */
#define NCHUNK  32
#define DC      32              /* D per scan chunk */
#define TS      32              /* scan steps per tile */
#define RMS_EPS 1.1920929e-07f

// k_scan dynamic smem layout (floats) — proven 104KB footprint
#define XS_OFF   0            /* 2 x 32 x 32   = 2048  */
#define BS_OFF   2048         /* 2 x 32 x 128  = 8192  */
#define OUT_OFF  10240        /* 4 x 32 x 128  = 16384 */
#define SCAN_SMEM_BYTES (26624 * 4)   /* 104 KB */

// ---------------- scratch (static device arrays; no runtime alloc) ----------------
__device__ float          g_x   [ROWS*D_MODEL];     // gathered embeddings, 67MB
__device__ float          g_bt  [ROWS*STATE];       // sigmoid(x @ W_B^T)/1024, 8MB
__device__ float          g_hm  [ROWS*STATE];       // reduced state means, 8MB
__device__ float          g_wbt [D_MODEL*STATE];    // W_B transposed: [k][n]
__device__ float          g_wct [STATE*D_MODEL];    // W_C transposed: [n][d]
__device__ __nv_bfloat16  g_part[NCHUNK*ROWS*STATE];// per-chunk partial sums, 134MB

// ---------------- helpers ----------------
__device__ __forceinline__ unsigned long long pk2(float lo, float hi) {
    unsigned long long r; asm("mov.b64 %0,{%1,%2};" : "=l"(r) : "f"(lo), "f"(hi)); return r;
}
__device__ __forceinline__ void upk2(unsigned long long v, float& lo, float& hi) {
    asm("mov.b64 {%0,%1},%2;" : "=f"(lo), "=f"(hi) : "l"(v));
}
__device__ __forceinline__ unsigned long long fma2(unsigned long long a, unsigned long long b, unsigned long long c) {
    unsigned long long r; asm("fma.rn.f32x2 %0,%1,%2,%3;" : "=l"(r) : "l"(a), "l"(b), "l"(c)); return r;
}
__device__ __forceinline__ unsigned long long mul2(unsigned long long a, unsigned long long b) {
    unsigned long long r; asm("mul.rn.f32x2 %0,%1,%2;" : "=l"(r) : "l"(a), "l"(b)); return r;
}
__device__ __forceinline__ unsigned long long add2(unsigned long long a, unsigned long long b) {
    unsigned long long r; asm("add.rn.f32x2 %0,%1,%2;" : "=l"(r) : "l"(a), "l"(b)); return r;
}
__device__ __forceinline__ float sigmoidf_(float x) { return 1.0f / (1.0f + __expf(-x)); }

__device__ __forceinline__ void cpasync16(void* smem, const void* gmem) {
    unsigned s = (unsigned)__cvta_generic_to_shared(smem);
    asm volatile("cp.async.cg.shared.global [%0],[%1],16;" :: "r"(s), "l"(gmem));
}
#define CP_COMMIT() asm volatile("cp.async.commit_group;")
#define CP_WAIT0()  asm volatile("cp.async.wait_group 0;")

// ---------------- K0: transpose weights ----------------
__global__ void k_prep(const float* __restrict__ WB, const float* __restrict__ WC) {
    int i = blockIdx.x * 256 + threadIdx.x;            // 131072 total
    if (i < D_MODEL * STATE) {
        int k = i >> 7, n = i & 127;                    // g_wbt[k][n] = W_B[n][k]
        g_wbt[i] = WB[n * D_MODEL + k];
        int nn = i >> 10, d = i & 1023;                 // g_wct[n][d] = W_C[d][n]
        g_wct[i] = WC[d * STATE + nn];
    }
}

// ---------------- K1: embedding gather ----------------
__global__ void k_gather(const int* __restrict__ tokens, const float* __restrict__ emb) {
    int row = blockIdx.x;
    int tok = tokens[row];
    const float4* src = (const float4*)(emb + (size_t)tok * D_MODEL);
    float4* dst = (float4*)(g_x + (size_t)row * D_MODEL);
    dst[threadIdx.x] = src[threadIdx.x];                // 256 thr x 16B = 4KB
}

// ---------------- K2: Bt = sigmoid(x @ W_B^T)/1024  [16384x1024]x[1024x128] ----------------
// 256 threads, 8x8 micro-tile (best measured).
__global__ void __launch_bounds__(256, 1) k_gemm_bt() {
    __shared__ float As[2][128 * 8];   // [row][kk]
    __shared__ float Bs[2][8 * 128];   // [kk][n]
    int t = threadIdx.x;
    int row0 = blockIdx.x * 128;
    int tr = t >> 4, tc = t & 15;

    unsigned long long acc[8][4];
    #pragma unroll
    for (int i = 0; i < 8; i++)
        #pragma unroll
        for (int j = 0; j < 4; j++) acc[i][j] = 0ull;

    {
        int r = t >> 1, q = t & 1;
        cpasync16(&As[0][r * 8 + q * 4], &g_x[(size_t)(row0 + r) * D_MODEL + q * 4]);
        int kk = t >> 5, q2 = t & 31;
        cpasync16(&Bs[0][kk * 128 + q2 * 4], &g_wbt[kk * STATE + q2 * 4]);
        CP_COMMIT();
    }

    const int NT = D_MODEL / 8;   // 128 k-tiles
    for (int kt = 0; kt < NT; kt++) {
        CP_WAIT0();
        __syncthreads();
        if (kt + 1 < NT) {
            int k0 = (kt + 1) * 8, buf = (kt + 1) & 1;
            int r = t >> 1, q = t & 1;
            cpasync16(&As[buf][r * 8 + q * 4], &g_x[(size_t)(row0 + r) * D_MODEL + k0 + q * 4]);
            int kk = t >> 5, q2 = t & 31;
            cpasync16(&Bs[buf][kk * 128 + q2 * 4], &g_wbt[(k0 + kk) * STATE + q2 * 4]);
            CP_COMMIT();
        }
        const float* Ab = &As[kt & 1][0];
        const float* Bb = &Bs[kt & 1][0];
        #pragma unroll
        for (int kk = 0; kk < 8; kk++) {
            float4 b0 = *(const float4*)&Bb[kk * 128 + tc * 8];
            float4 b1 = *(const float4*)&Bb[kk * 128 + tc * 8 + 4];
            unsigned long long bp[4] = { pk2(b0.x, b0.y), pk2(b0.z, b0.w),
                                         pk2(b1.x, b1.y), pk2(b1.z, b1.w) };
            #pragma unroll
            for (int i = 0; i < 8; i++) {
                float a = Ab[(tr * 8 + i) * 8 + kk];
                unsigned long long ad = pk2(a, a);
                #pragma unroll
                for (int j = 0; j < 4; j++) acc[i][j] = fma2(ad, bp[j], acc[i][j]);
            }
        }
        __syncthreads();
    }

    // epilogue: sigmoid * (1/1024) + store  (1/1024 folded: linear recurrence scales h,
    // so the scan's emitted partial sums come out already in mean units)
    #pragma unroll
    for (int i = 0; i < 8; i++) {
        int row = row0 + tr * 8 + i;
        float o[8];
        #pragma unroll
        for (int j = 0; j < 4; j++) upk2(acc[i][j], o[2 * j], o[2 * j + 1]);
        #pragma unroll
        for (int j = 0; j < 8; j++) o[j] = sigmoidf_(o[j]) * 0.0009765625f;
        float* dst = &g_bt[(size_t)row * STATE + tc * 8];
        *(float4*)(dst)     = make_float4(o[0], o[1], o[2], o[3]);
        *(float4*)(dst + 4) = make_float4(o[4], o[5], o[6], o[7]);
    }
}

// ---------------- K3: the scan ----------------
// grid = 128 CTAs: (b, chunk). 512 threads: (quarter, n). Quarter owns 8 d's (4 f32x2).
// Compute loop has NO smem stores (emissions buffered in a 32-reg array) so the
// compiler can hoist LDS loads arbitrarily deep; stores + flush happen after.
__global__ void __launch_bounds__(512, 1) k_scan(const float* __restrict__ A_log) {
    extern __shared__ float sm[];

    int tid = threadIdx.x;
    int qt  = tid >> 7;                    // 0..3: which 8-d sub-chunk
    int nid = tid & 127;                   // state index n
    int c = blockIdx.x & 31;               // chunk
    int b = blockIdx.x >> 5;               // batch
    int d0 = c * DC;
    int dbase = d0 + qt * 8;
    int rbase = b * SEQ;

    // decay factors (4 pairs over d)
    unsigned long long a2[4], h2[4];
    #pragma unroll
    for (int j = 0; j < 4; j++) {
        float alo = sigmoidf_(A_log[(dbase + 2 * j)     * STATE + nid]);
        float ahi = sigmoidf_(A_log[(dbase + 2 * j + 1) * STATE + nid]);
        a2[j] = pk2(alo, ahi);
        h2[j] = 0ull;
    }

    // prologue: tile 0  (xs tile = 32x32 f32 = 4KB; bs tile = 32x128 f32 = 16KB)
    {
        if (tid < 256) {
            int ss = tid >> 3, q = tid & 7;
            cpasync16(&sm[XS_OFF + ss * 32 + q * 4],
                      &g_x[(size_t)(rbase + ss) * D_MODEL + d0 + q * 4]);
        }
        #pragma unroll
        for (int jj = 0; jj < 2; jj++) {
            int idx = tid + 512 * jj, s2 = idx >> 5, q2 = idx & 31;
            cpasync16(&sm[BS_OFF + s2 * 128 + q2 * 4],
                      &g_bt[(size_t)(rbase + s2) * STATE + q2 * 4]);
        }
        CP_COMMIT();
    }

    const int NT = SEQ / TS;   // 128 tiles
    for (int tt = 0; tt < NT; tt++) {
        CP_WAIT0();
        __syncthreads();   // tile data ready; also: prev flush done -> outs reusable
        if (tt + 1 < NT) {
            int s0n = (tt + 1) * TS, buf = (tt + 1) & 1;
            if (tid < 256) {
                int ss = tid >> 3, q = tid & 7;
                cpasync16(&sm[XS_OFF + buf * 1024 + ss * 32 + q * 4],
                          &g_x[(size_t)(rbase + s0n + ss) * D_MODEL + d0 + q * 4]);
            }
            #pragma unroll
            for (int jj = 0; jj < 2; jj++) {
                int idx = tid + 512 * jj, s2 = idx >> 5, q2 = idx & 31;
                cpasync16(&sm[BS_OFF + buf * 4096 + s2 * 128 + q2 * 4],
                          &g_bt[(size_t)(rbase + s0n + s2) * STATE + q2 * 4]);
            }
            CP_COMMIT();
        }
        int cur = tt & 1;
        const float* xb = &sm[XS_OFF + cur * 1024];
        const float* bb = &sm[BS_OFF + cur * 4096];
        float* ob = &sm[OUT_OFF + qt * 4096];

        // compute phase: pure LDS->FFMA2 stream, emissions kept in registers
        float stv[TS];
        #pragma unroll
        for (int ss = 0; ss < TS; ss++) {
            float btv = bb[ss * 128 + nid];
            ulonglong2 xva = *(const ulonglong2*)&xb[ss * 32 + qt * 8];
            ulonglong2 xvb = *(const ulonglong2*)&xb[ss * 32 + qt * 8 + 4];
            unsigned long long bt2 = pk2(btv, btv);
            h2[0] = fma2(a2[0], h2[0], mul2(bt2, xva.x));
            h2[1] = fma2(a2[1], h2[1], mul2(bt2, xva.y));
            h2[2] = fma2(a2[2], h2[2], mul2(bt2, xvb.x));
            h2[3] = fma2(a2[3], h2[3], mul2(bt2, xvb.y));
            unsigned long long st = add2(add2(h2[0], h2[1]), add2(h2[2], h2[3]));
            float lo, hi; upk2(st, lo, hi);
            stv[ss] = lo + hi;                // already in mean units (bt folded)
        }
        // store phase: burst the 32 emissions to the quarter's out slab
        #pragma unroll
        for (int ss = 0; ss < TS; ss++) ob[ss * 128 + nid] = stv[ss];
        __syncthreads();
        // flush: combine 4 quarters in fp32, cvt bf16, 16B/thread to g_part
        {
            int s = tid >> 4, g = tid & 15;   // 32 rows x 16 thr, 8 n each
            float w[8];
            #pragma unroll
            for (int k = 0; k < 8; k++) w[k] = 0.0f;
            #pragma unroll
            for (int q = 0; q < 4; q++) {
                const float4* p = (const float4*)&sm[OUT_OFF + q * 4096 + s * 128 + g * 8];
                float4 v0 = p[0], v1 = p[1];
                w[0] += v0.x; w[1] += v0.y; w[2] += v0.z; w[3] += v0.w;
                w[4] += v1.x; w[5] += v1.y; w[6] += v1.z; w[7] += v1.w;
            }
            __nv_bfloat162 p0 = __floats2bfloat162_rn(w[0], w[1]);
            __nv_bfloat162 p1 = __floats2bfloat162_rn(w[2], w[3]);
            __nv_bfloat162 p2 = __floats2bfloat162_rn(w[4], w[5]);
            __nv_bfloat162 p3 = __floats2bfloat162_rn(w[6], w[7]);
            uint4 pk;
            pk.x = *(unsigned*)&p0; pk.y = *(unsigned*)&p1;
            pk.z = *(unsigned*)&p2; pk.w = *(unsigned*)&p3;
            size_t row = (size_t)c * ROWS + rbase + tt * TS + s;
            ((uint4*)g_part)[row * 16 + g] = pk;
        }
    }
}

// ---------------- K4: reduce partials -> hm (2 n per thread, 4B loads) ----------------
__global__ void k_reduce() {
    int g = blockIdx.x * 256 + threadIdx.x;   // 4096 blocks => 1.05M threads
    int row = g >> 6, np = g & 63;            // np: pair of adjacent n
    float s0 = 0.0f, s1 = 0.0f;
    #pragma unroll
    for (int c = 0; c < NCHUNK; c++) {
        unsigned v = *(const unsigned*)&g_part[((size_t)c * ROWS + row) * STATE + np * 2];
        __nv_bfloat162 p = *(__nv_bfloat162*)&v;
        s0 += __bfloat162float(p.x);
        s1 += __bfloat162float(p.y);
    }
    *(float2*)&g_hm[(size_t)row * STATE + np * 2] = make_float2(s0, s1);
}

// ---------------- K5: y = hm @ W_C^T + D*x  (pre-norm), [16384x128]x[128x1024] ----------------
__global__ void __launch_bounds__(256, 1) k_gemm_y(float* __restrict__ out,
                                                   const float* __restrict__ Dp) {
    __shared__ float As[2][128 * 8];   // hm rows [row][kk]
    __shared__ float Bs[2][8 * 128];   // wct [kk][d]
    int t = threadIdx.x;
    int mt = blockIdx.x >> 3;
    int nt = blockIdx.x & 7;
    int row0 = mt * 128;
    int d0 = nt * 128;
    int tr = t >> 4, tc = t & 15;

    unsigned long long acc[8][4];
    #pragma unroll
    for (int i = 0; i < 8; i++)
        #pragma unroll
        for (int j = 0; j < 4; j++) acc[i][j] = 0ull;

    {
        int r = t >> 1, q = t & 1;
        cpasync16(&As[0][r * 8 + q * 4], &g_hm[(size_t)(row0 + r) * STATE + q * 4]);
        int kk = t >> 5, q2 = t & 31;
        cpasync16(&Bs[0][kk * 128 + q2 * 4], &g_wct[(size_t)kk * D_MODEL + d0 + q2 * 4]);
        CP_COMMIT();
    }

    const int NT = STATE / 8;  // 16 k-tiles
    for (int kt = 0; kt < NT; kt++) {
        CP_WAIT0();
        __syncthreads();
        if (kt + 1 < NT) {
            int k0 = (kt + 1) * 8, buf = (kt + 1) & 1;
            int r = t >> 1, q = t & 1;
            cpasync16(&As[buf][r * 8 + q * 4], &g_hm[(size_t)(row0 + r) * STATE + k0 + q * 4]);
            int kk = t >> 5, q2 = t & 31;
            cpasync16(&Bs[buf][kk * 128 + q2 * 4], &g_wct[(size_t)(k0 + kk) * D_MODEL + d0 + q2 * 4]);
            CP_COMMIT();
        }
        const float* Ab = &As[kt & 1][0];
        const float* Bb = &Bs[kt & 1][0];
        #pragma unroll
        for (int kk = 0; kk < 8; kk++) {
            float4 b0 = *(const float4*)&Bb[kk * 128 + tc * 8];
            float4 b1 = *(const float4*)&Bb[kk * 128 + tc * 8 + 4];
            unsigned long long bp[4] = { pk2(b0.x, b0.y), pk2(b0.z, b0.w),
                                         pk2(b1.x, b1.y), pk2(b1.z, b1.w) };
            #pragma unroll
            for (int i = 0; i < 8; i++) {
                float a = Ab[(tr * 8 + i) * 8 + kk];
                unsigned long long ad = pk2(a, a);
                #pragma unroll
                for (int j = 0; j < 4; j++) acc[i][j] = fma2(ad, bp[j], acc[i][j]);
            }
        }
        __syncthreads();
    }

    // epilogue: + D_param*x, store pre-norm y
    float4 dpa = *(const float4*)&Dp[d0 + tc * 8];
    float4 dpb = *(const float4*)&Dp[d0 + tc * 8 + 4];
    #pragma unroll
    for (int i = 0; i < 8; i++) {
        int row = row0 + tr * 8 + i;
        const float* xr = &g_x[(size_t)row * D_MODEL + d0 + tc * 8];
        float4 xa = *(const float4*)xr;
        float4 xb = *(const float4*)(xr + 4);
        float o[8];
        #pragma unroll
        for (int j = 0; j < 4; j++) upk2(acc[i][j], o[2 * j], o[2 * j + 1]);
        o[0] += dpa.x * xa.x; o[1] += dpa.y * xa.y; o[2] += dpa.z * xa.z; o[3] += dpa.w * xa.w;
        o[4] += dpb.x * xb.x; o[5] += dpb.y * xb.y; o[6] += dpb.z * xb.z; o[7] += dpb.w * xb.w;
        float* dst = out + (size_t)row * D_MODEL + d0 + tc * 8;
        *(float4*)(dst)     = make_float4(o[0], o[1], o[2], o[3]);
        *(float4*)(dst + 4) = make_float4(o[4], o[5], o[6], o[7]);
    }
}

// ---------------- K6: RMSNorm in place ----------------
__global__ void k_rms(float* __restrict__ out, const float* __restrict__ w) {
    int row = blockIdx.x;
    int t = threadIdx.x;
    float4* p = (float4*)(out + (size_t)row * D_MODEL);
    float4 v = p[t];
    float ss = v.x * v.x + v.y * v.y + v.z * v.z + v.w * v.w;
    #pragma unroll
    for (int off = 16; off > 0; off >>= 1) ss += __shfl_xor_sync(0xffffffffu, ss, off);
    __shared__ float red[8];
    if ((t & 31) == 0) red[t >> 5] = ss;
    __syncthreads();
    if (t < 32) {
        float v2 = (t < 8) ? red[t] : 0.0f;
        #pragma unroll
        for (int off = 4; off > 0; off >>= 1) v2 += __shfl_xor_sync(0xffffffffu, v2, off);
        if (t == 0) red[0] = v2;
    }
    __syncthreads();
    float sc = rsqrtf(red[0] * (1.0f / 1024.0f) + RMS_EPS);
    const float4* w4 = (const float4*)w;
    float4 wv = w4[t];
    v.x *= sc * wv.x; v.y *= sc * wv.y; v.z *= sc * wv.z; v.w *= sc * wv.w;
    p[t] = v;
}

// ---------------- launch ----------------
extern "C" void kernel_launch(void* const* d_in, const int* in_sizes, int n_in,
                              void* d_out, int out_size) {
    (void)in_sizes; (void)n_in; (void)out_size;
    const int*   tokens = (const int*)  d_in[0];
    const float* emb    = (const float*)d_in[1];
    const float* A_log  = (const float*)d_in[2];
    const float* W_B    = (const float*)d_in[3];
    const float* W_C    = (const float*)d_in[4];
    const float* Dp     = (const float*)d_in[5];
    const float* nw     = (const float*)d_in[6];
    float* out = (float*)d_out;

    // opt-in to >48KB dynamic smem for k_scan (idempotent; no stream op, capture-safe)
    cudaFuncSetAttribute(k_scan, cudaFuncAttributeMaxDynamicSharedMemorySize,
                         SCAN_SMEM_BYTES);

    k_prep<<<512, 256>>>(W_B, W_C);
    k_gather<<<ROWS, 256>>>(tokens, emb);
    k_gemm_bt<<<ROWS / 128, 256>>>();
    k_scan<<<BATCH * NCHUNK, 512, SCAN_SMEM_BYTES>>>(A_log);
    k_reduce<<<ROWS * STATE / 512, 256>>>();
    k_gemm_y<<<(ROWS / 128) * (D_MODEL / 128), 256>>>(out, Dp);
    k_rms<<<ROWS, 256>>>(out, nw);
}